// round 14
// baseline (speedup 1.0000x reference)
#include <cuda_runtime.h>
#include <cuda_bf16.h>
#include <cuda_fp16.h>
#include <mma.h>
#include <cstddef>
#include <cstdint>

using namespace nvcuda;

#define BB    32
#define TKK   1024
#define HH    512
#define EE    256
#define VOCAB 50257
#define M_ENC (BB * TKK)   // 32768
#define NSLAB 393          // ceil(VOCAB/128)

#define FE_BLOCKS 256
#define FE_THREADS 256
#define FE_NT (FE_BLOCKS * FE_THREADS)

// ---------------- scratch (__device__ globals) ------------------------------
__device__ float g_xinT[(HH + EE) * BB];
__device__ float g_hT[HH * BB];
__device__ float g_xT[EE * BB];
__device__ float g_giT[3 * HH * BB];
__device__ float g_ghT[3 * HH * BB];
__device__ float g_hnewT[HH * BB];
__device__ float g_dec[BB * HH];
__device__ float g_scores[BB * TKK];
__device__ float g_concatT[2 * HH * BB];
__device__ float g_out1[BB * HH];
__device__ float g_logits[(size_t)BB * VOCAB];
__device__ __half g_whh[HH * HH];                 // fp16 Wh [n][k]
__device__ __half g_ench[(size_t)M_ENC * HH];     // fp16 enc
__device__ float g_smx[BB * 400];
__device__ float g_sms[BB * 400];

__device__ unsigned g_barcnt = 0;
__device__ unsigned g_barsense = 0;

__device__ __forceinline__ float sigmoidf_(float x) { return 1.f / (1.f + __expf(-x)); }
__device__ __forceinline__ float tanh_fast(float x) {
    float r; asm("tanh.approx.f32 %0, %1;" : "=f"(r) : "f"(x)); return r;
}
__device__ __forceinline__ void cp16(uint32_t dst, const void* src) {
    asm volatile("cp.async.cg.shared.global [%0], [%1], 16;" :: "r"(dst), "l"(src));
}
__device__ __forceinline__ void cp_commit() { asm volatile("cp.async.commit_group;"); }
template<int N> __device__ __forceinline__ void cp_wait() {
    asm volatile("cp.async.wait_group %0;" :: "n"(N));
}
__device__ __forceinline__ uint32_t packh(float a, float b) {
    __half2 t = __floats2half2_rn(a, b);
    return *(uint32_t*)&t;
}

// ---------------- grid-wide barrier -----------------------------------------
__device__ __forceinline__ void grid_bar(unsigned* sense) {
    __syncthreads();
    if (threadIdx.x == 0) {
        __threadfence();
        unsigned target = *sense ^ 1u;
        if (atomicAdd(&g_barcnt, 1u) == FE_BLOCKS - 1) {
            atomicExch(&g_barcnt, 0u);
            __threadfence();
            atomicExch(&g_barsense, target);
        } else {
            while (atomicAdd(&g_barsense, 0u) != target) {}
        }
        __threadfence();
        *sense = target;
    }
    __syncthreads();
}

__device__ __forceinline__ float dotk(const float4* __restrict__ w4,
                                      const float* __restrict__ a, int iters) {
    float a0 = 0.f, a1 = 0.f, a2 = 0.f, a3 = 0.f;
#pragma unroll 16
    for (int i = 0; i < iters; i++) {
        float4 w = w4[i];
        const float* ak = a + (i << 7);
        a0 += w.x * ak[0];
        a1 += w.y * ak[32];
        a2 += w.z * ak[64];
        a3 += w.w * ak[96];
    }
    return (a0 + a1) + (a2 + a3);
}

// ---------------- convert enc -> fp16 (side stream) -------------------------
__global__ void k_convert_enc(const float* __restrict__ enc, int base) {
    size_t i = (size_t)base + (size_t)blockIdx.x * blockDim.x + threadIdx.x;
    const float4* s = (const float4*)(enc) + i * 2;
    float4 v0 = s[0], v1 = s[1];
    *(uint4*)(g_ench + i * 8) = make_uint4(packh(v0.x, v0.y), packh(v0.z, v0.w),
                                           packh(v1.x, v1.y), packh(v1.z, v1.w));
}

// ---------------- persistent front-end (main stream) ------------------------
__global__ __launch_bounds__(FE_THREADS) void k_frontend(
    const int* __restrict__ yt, const float* __restrict__ c_t_1,
    const float* __restrict__ s_t_1, const float* __restrict__ emb,
    const float* __restrict__ xc_w, const float* __restrict__ xc_b,
    const float* __restrict__ w_ih, const float* __restrict__ b_ih,
    const float* __restrict__ w_hh, const float* __restrict__ b_hh,
    const float* __restrict__ dp_w, const float* __restrict__ dp_b,
    const float* __restrict__ out1_b, const float* __restrict__ Wh,
    float* __restrict__ out_st, float* __restrict__ out_ct)
{
    int tid = threadIdx.x;
    int gt = blockIdx.x * FE_THREADS + tid;
    int gw = gt >> 5, lane = gt & 31;
    unsigned sense = 0;
    if (tid == 0) sense = atomicAdd(&g_barsense, 0u);

    // ---- S0: bias init, transposes, Wh->fp16, zero scores/ct/concat-hi ----
    for (int idx = gt; idx < 4352 * 32; idx += FE_NT) {
        int n = idx >> 5, b = idx & 31;
        if (n < EE)     { g_xT[n * 32 + b] = xc_b[n];  continue; }  n -= EE;
        if (n < 3 * HH) { g_giT[n * 32 + b] = b_ih[n]; continue; }  n -= 3 * HH;
        if (n < 3 * HH) { g_ghT[n * 32 + b] = b_hh[n]; continue; }  n -= 3 * HH;
        if (n < HH)     { g_dec[b * HH + n] = dp_b[n]; continue; }  n -= HH;
        g_out1[b * HH + n] = out1_b[n];
    }
    for (int idx = gt; idx < (HH + EE) * BB; idx += FE_NT) {
        int k = idx >> 5, b = idx & 31;
        g_xinT[idx] = (k < HH) ? c_t_1[b * HH + k]
                               : emb[(size_t)yt[b] * EE + (k - HH)];
    }
    for (int idx = gt; idx < HH * BB; idx += FE_NT) {
        int k = idx >> 5, b = idx & 31;
        g_hT[idx] = s_t_1[b * HH + k];
    }
    for (int i = gt; i < HH * HH / 2; i += FE_NT) {
        float2 v = *(const float2*)(Wh + (size_t)i * 2);
        *(__half2*)(g_whh + (size_t)i * 2) = __floats2half2_rn(v.x, v.y);
    }
    for (int idx = gt; idx < BB * TKK; idx += FE_NT) g_scores[idx] = 0.f;
    for (int idx = gt; idx < HH * BB; idx += FE_NT) {
        g_concatT[HH * BB + idx] = 0.f;            // ct half of concat
        out_ct[idx] = 0.f;                          // [b][h] zero for atomics
    }
    grid_bar(&sense);

    // ---- S1: x ----
    {
        int n = gw >> 3, sp = gw & 7;
        int k0 = sp * 96;
        float r = dotk((const float4*)(xc_w + (size_t)n * (HH + EE) + k0),
                       g_xinT + k0 * 32 + lane, 24);
        atomicAdd(&g_xT[n * 32 + lane], r);
    }
    grid_bar(&sense);

    // ---- S2: gi + gh ----
    for (int u = gw; u < 9216; u += 2048) {
        if (u < 3072) {
            int n = u >> 1, sp = u & 1, k0 = sp * 128;
            float r = dotk((const float4*)(w_ih + (size_t)n * EE + k0),
                           g_xT + k0 * 32 + lane, 32);
            atomicAdd(&g_giT[n * 32 + lane], r);
        } else {
            int v = u - 3072;
            int n = v >> 2, sp = v & 3, k0 = sp * 128;
            float r = dotk((const float4*)(w_hh + (size_t)n * HH + k0),
                           g_hT + k0 * 32 + lane, 32);
            atomicAdd(&g_ghT[n * 32 + lane], r);
        }
    }
    grid_bar(&sense);

    // ---- S3: GRU ----
    if (gt < HH * BB) {
        int j = gt >> 5, b = gt & 31;
        float ir = g_giT[j * BB + b],             hr = g_ghT[j * BB + b];
        float iz = g_giT[(HH + j) * BB + b],      hz = g_ghT[(HH + j) * BB + b];
        float in_ = g_giT[(2 * HH + j) * BB + b], hn = g_ghT[(2 * HH + j) * BB + b];
        float r = sigmoidf_(ir + hr);
        float z = sigmoidf_(iz + hz);
        float nn = tanhf(in_ + r * hn);
        float h = g_hT[j * BB + b];
        float hv = (1.f - z) * nn + z * h;
        g_hnewT[j * BB + b] = hv;
        g_concatT[j * BB + b] = hv;
        out_st[b * HH + j] = hv;
    }
    grid_bar(&sense);

    // ---- S4: dec ----
    {
        int n = gw >> 2, sp = gw & 3, k0 = sp * 128;
        float r = dotk((const float4*)(dp_w + (size_t)n * HH + k0),
                       g_hnewT + k0 * 32 + lane, 32);
        atomicAdd(&g_dec[lane * HH + n], r);
    }
}

// ---------------- split-K small GEMM (out1) ---------------------------------
__global__ __launch_bounds__(256) void k_bsplit(float* __restrict__ yT,
                                                float* __restrict__ yR,
                                                const float* __restrict__ AT,
                                                const float* __restrict__ W,
                                                int N, int K) {
    int warp = threadIdx.x >> 5, lane = threadIdx.x & 31;
    int n = blockIdx.x * 8 + warp;
    int kchunk = K / gridDim.y;
    int k0 = blockIdx.y * kchunk;
    float r = dotk((const float4*)(W + (size_t)n * K + k0),
                   AT + k0 * 32 + lane, kchunk >> 2);
    if (yT) atomicAdd(&yT[n * 32 + lane], r);
    if (yR) atomicAdd(&yR[(size_t)lane * N + n], r);
}

// ---------------- fused attention v3 (captured launch) ----------------------
#define F3_STG   2304
#define F3_STGSZ 25600
#define F3_SMEM  (F3_STG + 2 * F3_STGSZ)     // 53504

#define F3_ISSUE(c, st) do {                                                    \
    uint32_t sb_ = smb + F3_STG + (st) * F3_STGSZ;                              \
    _Pragma("unroll")                                                           \
    for (int i_ = 0; i_ < 5; i_++) {                                            \
        int s_ = tid + (i_ << 8);                                               \
        if (i_ == 0) {                                                          \
            int r_ = s_ >> 2, q_ = s_ & 3;                                      \
            cp16(sb_ + r_ * 80 + q_ * 16,                                       \
                 g_ench + (m0 + r_) * HH + (c) * 32 + q_ * 8);                  \
        } else {                                                                \
            int t_ = s_ - 256, r_ = t_ >> 2, q_ = t_ & 3;                       \
            cp16(sb_ + 5120 + r_ * 80 + q_ * 16,                                \
                 g_whh + (size_t)(n0 + r_) * HH + (c) * 32 + q_ * 8);           \
        }                                                                       \
    }                                                                           \
    cp_commit();                                                                \
} while (0)

__global__ __launch_bounds__(256, 3) void k_fat3(const float* __restrict__ vw) {
    extern __shared__ char sm[];
    uint32_t smb = (uint32_t)__cvta_generic_to_shared(sm);
    float* sdec = (float*)(sm + 0);
    float* sv   = (float*)(sm + 1024);
    float* srow = (float*)(sm + 2048);

    int tid = threadIdx.x, warp = tid >> 5, lane = tid & 31;
    int bt = blockIdx.x, n0 = blockIdx.y << 8;
    int b = bt >> 4;
    size_t m0 = (size_t)bt * 64;

    sv[tid]   = vw[n0 + tid];
    sdec[tid] = g_dec[b * HH + n0 + tid];
    if (tid < 64) srow[tid] = 0.f;

    int wm = warp >> 2, wn = warp & 3;    // warp tile: 32 rows x 64 cols
    wmma::fragment<wmma::accumulator, 16, 16, 16, __half> acc[2][4];
#pragma unroll
    for (int i = 0; i < 2; i++)
#pragma unroll
        for (int j = 0; j < 4; j++) wmma::fill_fragment(acc[i][j], __float2half(0.f));

    F3_ISSUE(0, 0);

    for (int c = 0; c < 16; c++) {
        cp_wait<0>();
        __syncthreads();     // publishes stage c; retires stage c-1
        if (c < 15) F3_ISSUE(c + 1, (c + 1) & 1);
        const __half* ab = (const __half*)(sm + F3_STG + (c & 1) * F3_STGSZ);
        const __half* bb = ab + 2560;
#pragma unroll
        for (int kk = 0; kk < 32; kk += 16) {
            wmma::fragment<wmma::matrix_a, 16, 16, 16, __half, wmma::row_major> af[2];
#pragma unroll
            for (int i = 0; i < 2; i++)
                wmma::load_matrix_sync(af[i], ab + (wm * 32 + i * 16) * 40 + kk, 40);
#pragma unroll
            for (int j = 0; j < 4; j++) {
                wmma::fragment<wmma::matrix_b, 16, 16, 16, __half, wmma::col_major> bf;
                wmma::load_matrix_sync(bf, bb + (wn * 64 + j * 16) * 40 + kk, 40);
                wmma::mma_sync(acc[0][j], af[0], bf, acc[0][j]);
                wmma::mma_sync(acc[1][j], af[1], bf, acc[1][j]);
            }
        }
    }
    __syncthreads();   // protect stage buffers before scratch reuse

    __half* scr = (__half*)(sm + F3_STG) + warp * 1088;   // [16][68] halfs
#pragma unroll
    for (int i = 0; i < 2; i++) {
#pragma unroll
        for (int j = 0; j < 4; j++)
            wmma::store_matrix_sync(scr + j * 16, acc[i][j], 68, wmma::mem_row_major);
        __syncwarp();
        int row = lane >> 1, hf = lane & 1;
        const __half* sr = scr + row * 68;
        float p = 0.f;
#pragma unroll
        for (int c = 0; c < 32; c++) {
            int cl = wn * 64 + hf * 32 + c;
            p += sv[cl] * tanh_fast(__half2float(sr[hf * 32 + c]) + sdec[cl]);
        }
        p += __shfl_xor_sync(0xffffffffu, p, 1);
        if (hf == 0) atomicAdd(&srow[wm * 32 + i * 16 + row], p);
        __syncwarp();
    }
    __syncthreads();
    if (tid < 64) atomicAdd(&g_scores[bt * 64 + tid], srow[tid]);
}

// ---------------- merged attn softmax + c_t partial --------------------------
__global__ __launch_bounds__(512) void k_attn_ct(float* __restrict__ out_attn,
                                                 float* __restrict__ out_ct) {
    __shared__ float satt[1024];
    __shared__ float red[16];
    __shared__ float sa[64];
    int c = blockIdx.x, b = blockIdx.y, tid = threadIdx.x;   // 512 thr

    float s0 = g_scores[b * TKK + tid];
    float s1 = g_scores[b * TKK + 512 + tid];
    float m = fmaxf(s0, s1);
#pragma unroll
    for (int o = 16; o; o >>= 1) m = fmaxf(m, __shfl_xor_sync(0xffffffffu, m, o));
    if ((tid & 31) == 0) red[tid >> 5] = m;
    __syncthreads();
    if (tid < 32) {
        float v = (tid < 16) ? red[tid] : -1e30f;
#pragma unroll
        for (int o = 8; o; o >>= 1) v = fmaxf(v, __shfl_xor_sync(0xffffffffu, v, o));
        if (tid == 0) red[0] = v;
    }
    __syncthreads();
    float mx = red[0];
    __syncthreads();
    float e0 = __expf(s0 - mx), e1 = __expf(s1 - mx);
    float sm = e0 + e1;
#pragma unroll
    for (int o = 16; o; o >>= 1) sm += __shfl_xor_sync(0xffffffffu, sm, o);
    if ((tid & 31) == 0) red[tid >> 5] = sm;
    __syncthreads();
    if (tid < 32) {
        float v = (tid < 16) ? red[tid] : 0.f;
#pragma unroll
        for (int o = 8; o; o >>= 1) v += __shfl_xor_sync(0xffffffffu, v, o);
        if (tid == 0) red[0] = v;
    }
    __syncthreads();
    float inv = 1.f / red[0];
    satt[tid] = e0 * inv;
    satt[512 + tid] = e1 * inv;
    __syncthreads();
    if (tid < 64) {
        float a = satt[c * 64 + tid];
        out_attn[b * TKK + c * 64 + tid] = a;
        sa[tid] = a;
    }
    __syncthreads();
    // partial c_t over this block's 64-t chunk
    const __half* e = g_ench + ((size_t)b * TKK + c * 64) * HH + tid;
    float acc = 0.f;
#pragma unroll 8
    for (int t = 0; t < 64; t++) acc += sa[t] * __half2float(e[(size_t)t * HH]);
    atomicAdd(&out_ct[b * HH + tid], acc);
    atomicAdd(&g_concatT[(HH + tid) * BB + b], acc);
}

// ---------------- logits via bf16 wmma + fused per-slab softmax stats -------
#define LG_SMEM (33280 + 20480)
__global__ __launch_bounds__(256) void k_logits_mma(const float* __restrict__ W,
                                                    const float* __restrict__ bias) {
    extern __shared__ char smraw[];
    __nv_bfloat16* As2 = (__nv_bfloat16*)smraw;                // [32][520]
    __nv_bfloat16* Ws  = (__nv_bfloat16*)(smraw + 33280);      // [2][128][40]
    float* stage = (float*)(smraw + 33280);                    // [32][136]

    int tid = threadIdx.x, warp = tid >> 5;
    int n0 = blockIdx.x * 128;
    for (int idx = tid; idx < BB * HH; idx += 256) {
        int r = idx >> 9, k = idx & 511;
        As2[r * 520 + k] = __float2bfloat16(g_out1[idx]);
    }

    wmma::fragment<wmma::accumulator, 16, 16, 16, float> acc[2];
    wmma::fill_fragment(acc[0], 0.f);
    wmma::fill_fragment(acc[1], 0.f);

    int lrow = tid >> 3, lq = tid & 7;
    float4 wreg[4];
#pragma unroll
    for (int p = 0; p < 4; p++) {
        int n = n0 + p * 32 + lrow;
        wreg[p] = (n < VOCAB) ? *(const float4*)(W + (size_t)n * HH + lq * 4)
                              : make_float4(0.f, 0.f, 0.f, 0.f);
    }
    for (int it = 0; it < 16; it++) {
        int cur = it & 1;
        __nv_bfloat16* wd = Ws + cur * (128 * 40);
#pragma unroll
        for (int p = 0; p < 4; p++) {
            __nv_bfloat16* d = wd + (p * 32 + lrow) * 40 + lq * 4;
            *(__nv_bfloat162*)d       = __floats2bfloat162_rn(wreg[p].x, wreg[p].y);
            *(__nv_bfloat162*)(d + 2) = __floats2bfloat162_rn(wreg[p].z, wreg[p].w);
        }
        if (it < 15) {
#pragma unroll
            for (int p = 0; p < 4; p++) {
                int n = n0 + p * 32 + lrow;
                wreg[p] = (n < VOCAB)
                    ? *(const float4*)(W + (size_t)n * HH + (it + 1) * 32 + lq * 4)
                    : make_float4(0.f, 0.f, 0.f, 0.f);
            }
        }
        __syncthreads();
#pragma unroll
        for (int kk = 0; kk < 32; kk += 16) {
            wmma::fragment<wmma::matrix_b, 16, 16, 16, __nv_bfloat16, wmma::col_major> bf;
            wmma::load_matrix_sync(bf, wd + (warp * 16) * 40 + kk, 40);
#pragma unroll
            for (int i = 0; i < 2; i++) {
                wmma::fragment<wmma::matrix_a, 16, 16, 16, __nv_bfloat16, wmma::row_major> af;
                wmma::load_matrix_sync(af, As2 + (i * 16) * 520 + it * 32 + kk, 520);
                wmma::mma_sync(acc[i], af, bf, acc[i]);
            }
        }
    }
    __syncthreads();
#pragma unroll
    for (int i = 0; i < 2; i++)
        wmma::store_matrix_sync(stage + (i * 16) * 136 + warp * 16, acc[i], 136,
                                wmma::mem_row_major);
    __syncthreads();
    for (int idx = tid; idx < 32 * 128; idx += 256) {
        int r = idx >> 7, c = idx & 127;
        int n = n0 + c;
        if (n < VOCAB)
            g_logits[(size_t)r * VOCAB + n] = stage[r * 136 + c] + bias[n];
    }
    // fused per-slab softmax stats: row = b, over this block's valid cols
    {
        int l = tid & 31;
        int row = (tid >> 5) * 4 + (l >> 3);   // 8 warps x 4 rows = 32 rows
        int c0 = l & 7;
        float mx = -1e30f;
        for (int c = c0; c < 128; c += 8) {
            int n = n0 + c;
            if (n < VOCAB) mx = fmaxf(mx, stage[row * 136 + c] + bias[n]);
        }
#pragma unroll
        for (int o = 4; o; o >>= 1) mx = fmaxf(mx, __shfl_xor_sync(0xffffffffu, mx, o));
        float sm = 0.f;
        for (int c = c0; c < 128; c += 8) {
            int n = n0 + c;
            if (n < VOCAB) sm += __expf(stage[row * 136 + c] + bias[n] - mx);
        }
#pragma unroll
        for (int o = 4; o; o >>= 1) sm += __shfl_xor_sync(0xffffffffu, sm, o);
        if (c0 == 0) {
            g_smx[row * 400 + blockIdx.x] = mx;
            g_sms[row * 400 + blockIdx.x] = sm;
        }
    }
}

// ---------------- vocab softmax normalize (reduces NSLAB partials) ----------
__global__ __launch_bounds__(256) void k_smB(float* __restrict__ out_fd) {
    __shared__ float red[16];
    int b = blockIdx.y, tid = threadIdx.x;
    // block-wide max over NSLAB partial maxima
    float m = -1e30f;
    for (int s = tid; s < NSLAB; s += 256) m = fmaxf(m, g_smx[b * 400 + s]);
#pragma unroll
    for (int o = 16; o; o >>= 1) m = fmaxf(m, __shfl_xor_sync(0xffffffffu, m, o));
    if ((tid & 31) == 0) red[tid >> 5] = m;
    __syncthreads();
    if (tid < 32) {
        float v = (tid < 8) ? red[tid] : -1e30f;
#pragma unroll
        for (int o = 4; o; o >>= 1) v = fmaxf(v, __shfl_xor_sync(0xffffffffu, v, o));
        if (tid == 0) red[0] = v;
    }
    __syncthreads();
    float M = red[0];
    __syncthreads();
    float s = 0.f;
    for (int sl = tid; sl < NSLAB; sl += 256)
        s += g_sms[b * 400 + sl] * __expf(g_smx[b * 400 + sl] - M);
#pragma unroll
    for (int o = 16; o; o >>= 1) s += __shfl_xor_sync(0xffffffffu, s, o);
    if ((tid & 31) == 0) red[tid >> 5] = s;
    __syncthreads();
    if (tid < 32) {
        float v = (tid < 8) ? red[tid] : 0.f;
#pragma unroll
        for (int o = 4; o; o >>= 1) v += __shfl_xor_sync(0xffffffffu, v, o);
        if (tid == 0) red[0] = v;
    }
    __syncthreads();
    float inv = 1.f / red[0];
    const float* lg = g_logits + (size_t)b * VOCAB;
    float* dst = out_fd + (size_t)b * VOCAB;
    int base = blockIdx.x * 2048;
#pragma unroll
    for (int j = 0; j < 8; j++) {
        int n = base + j * 256 + tid;
        if (n < VOCAB) dst[n] = __expf(lg[n] - M) * inv;
    }
}

// ---------------- launcher ---------------------------------------------------
extern "C" void kernel_launch(void* const* d_in, const int* in_sizes, int n_in,
                              void* d_out, int out_size) {
    const int*   y      = (const int*)d_in[0];
    const float* s_t_1  = (const float*)d_in[2];
    const float* enc    = (const float*)d_in[3];
    const float* c_t_1  = (const float*)d_in[4];
    const float* cov    = (const float*)d_in[5];
    const float* emb    = (const float*)d_in[7];
    const float* xc_w   = (const float*)d_in[8];
    const float* xc_b   = (const float*)d_in[9];
    const float* Wh_w   = (const float*)d_in[10];
    const float* w_ih   = (const float*)d_in[11];
    const float* w_hh   = (const float*)d_in[12];
    const float* b_ih   = (const float*)d_in[13];
    const float* b_hh   = (const float*)d_in[14];
    const float* dp_w   = (const float*)d_in[15];
    const float* dp_b   = (const float*)d_in[16];
    const float* v_w    = (const float*)d_in[17];
    const float* out1_w = (const float*)d_in[18];
    const float* out1_b = (const float*)d_in[19];
    const float* out2_w = (const float*)d_in[20];
    const float* out2_b = (const float*)d_in[21];

    float* out      = (float*)d_out;
    float* out_fd   = out;
    float* out_st   = out_fd + (size_t)BB * VOCAB;
    float* out_ct   = out_st + BB * HH;
    float* out_attn = out_ct + BB * HH;
    float* out_cov  = out_attn + BB * TKK;

    float *p_concatT, *p_out1;
    cudaGetSymbolAddress((void**)&p_concatT, g_concatT);
    cudaGetSymbolAddress((void**)&p_out1,    g_out1);

    static cudaStream_t s2 = nullptr;
    static cudaEvent_t evF = nullptr, evJ = nullptr;
    if (!s2) {
        cudaStreamCreateWithFlags(&s2, cudaStreamNonBlocking);
        cudaEventCreateWithFlags(&evF, cudaEventDisableTiming);
        cudaEventCreateWithFlags(&evJ, cudaEventDisableTiming);
        cudaFuncSetAttribute(k_fat3, cudaFuncAttributeMaxDynamicSharedMemorySize, F3_SMEM);
        cudaFuncSetAttribute(k_logits_mma, cudaFuncAttributeMaxDynamicSharedMemorySize, LG_SMEM);
    }

    // fork: converts + cov copy on side stream, front-end on main stream
    cudaEventRecord(evF, 0);
    cudaStreamWaitEvent(s2, evF, 0);
    k_convert_enc<<<4096, 256, 0, s2>>>(enc, 0);                           // launch 0
    k_convert_enc<<<4096, 256, 0, s2>>>(enc, 1048576);                     // launch 1
    cudaMemcpyAsync(out_cov, cov, (size_t)BB * TKK * sizeof(float),
                    cudaMemcpyDeviceToDevice, s2);
    cudaEventRecord(evJ, s2);
    k_frontend<<<FE_BLOCKS, FE_THREADS>>>(y, c_t_1, s_t_1, emb,
                                          xc_w, xc_b, w_ih, b_ih, w_hh, b_hh,
                                          dp_w, dp_b, out1_b, Wh_w,
                                          out_st, out_ct);                 // launch 2
    cudaStreamWaitEvent(0, evJ, 0);
    // join: fat3 needs both
    k_fat3<<<dim3(M_ENC / 64, 2), 256, F3_SMEM>>>(v_w);                    // launch 3 <- profiled
    k_attn_ct<<<dim3(16, BB), 512>>>(out_attn, out_ct);
    k_bsplit<<<dim3(HH / 8, 8), 256>>>(nullptr, p_out1, p_concatT, out1_w, HH, 2 * HH);
    k_logits_mma<<<(VOCAB + 127) / 128, 256, LG_SMEM>>>(out2_w, out2_b);
    k_smB<<<dim3(25, BB), 256>>>(out_fd);
}

// round 15
// speedup vs baseline: 1.0474x; 1.0474x over previous
#include <cuda_runtime.h>
#include <cuda_bf16.h>
#include <cuda_fp16.h>
#include <mma.h>
#include <cstddef>
#include <cstdint>

using namespace nvcuda;

#define BB    32
#define TKK   1024
#define HH    512
#define EE    256
#define VOCAB 50257
#define M_ENC (BB * TKK)   // 32768
#define NSLAB 393          // ceil(VOCAB/128)

#define FE_BLOCKS 256
#define FE_THREADS 256
#define FE_NT (FE_BLOCKS * FE_THREADS)

// ---------------- scratch (__device__ globals) ------------------------------
__device__ float g_xinT[(HH + EE) * BB];
__device__ float g_hT[HH * BB];
__device__ float g_xT[EE * BB];
__device__ float g_giT[3 * HH * BB];
__device__ float g_ghT[3 * HH * BB];
__device__ float g_hnewT[HH * BB];
__device__ float g_dec[BB * HH];
__device__ float g_scores[BB * TKK];
__device__ float g_concatT[2 * HH * BB];
__device__ float g_out1[BB * HH];
__device__ float g_logits[(size_t)BB * VOCAB];
__device__ __half g_whh[HH * HH];                 // fp16 Wh [n][k]
__device__ __half g_ench[(size_t)M_ENC * HH];     // fp16 enc
__device__ float g_smx[BB * 400];
__device__ float g_sms[BB * 400];

__device__ unsigned g_barcnt = 0;
__device__ unsigned g_barsense = 0;

__device__ __forceinline__ float sigmoidf_(float x) { return 1.f / (1.f + __expf(-x)); }
__device__ __forceinline__ float tanh_fast(float x) {
    float r; asm("tanh.approx.f32 %0, %1;" : "=f"(r) : "f"(x)); return r;
}
__device__ __forceinline__ void cp16(uint32_t dst, const void* src) {
    asm volatile("cp.async.cg.shared.global [%0], [%1], 16;" :: "r"(dst), "l"(src));
}
__device__ __forceinline__ void cp_commit() { asm volatile("cp.async.commit_group;"); }
template<int N> __device__ __forceinline__ void cp_wait() {
    asm volatile("cp.async.wait_group %0;" :: "n"(N));
}
__device__ __forceinline__ uint32_t packh(float a, float b) {
    __half2 t = __floats2half2_rn(a, b);
    return *(uint32_t*)&t;
}

// ---------------- grid-wide barrier -----------------------------------------
__device__ __forceinline__ void grid_bar(unsigned* sense) {
    __syncthreads();
    if (threadIdx.x == 0) {
        __threadfence();
        unsigned target = *sense ^ 1u;
        if (atomicAdd(&g_barcnt, 1u) == FE_BLOCKS - 1) {
            atomicExch(&g_barcnt, 0u);
            __threadfence();
            atomicExch(&g_barsense, target);
        } else {
            while (atomicAdd(&g_barsense, 0u) != target) {}
        }
        __threadfence();
        *sense = target;
    }
    __syncthreads();
}

__device__ __forceinline__ float dotk(const float4* __restrict__ w4,
                                      const float* __restrict__ a, int iters) {
    float a0 = 0.f, a1 = 0.f, a2 = 0.f, a3 = 0.f;
#pragma unroll 16
    for (int i = 0; i < iters; i++) {
        float4 w = w4[i];
        const float* ak = a + (i << 7);
        a0 += w.x * ak[0];
        a1 += w.y * ak[32];
        a2 += w.z * ak[64];
        a3 += w.w * ak[96];
    }
    return (a0 + a1) + (a2 + a3);
}

// ---------------- convert enc -> fp16 (side stream) -------------------------
__global__ void k_convert_enc(const float* __restrict__ enc, int base) {
    size_t i = (size_t)base + (size_t)blockIdx.x * blockDim.x + threadIdx.x;
    const float4* s = (const float4*)(enc) + i * 2;
    float4 v0 = s[0], v1 = s[1];
    *(uint4*)(g_ench + i * 8) = make_uint4(packh(v0.x, v0.y), packh(v0.z, v0.w),
                                           packh(v1.x, v1.y), packh(v1.z, v1.w));
}

// ---------------- zero scores (side stream) ---------------------------------
__global__ void k_zero_scores() {
    int i = blockIdx.x * 256 + threadIdx.x;
    ((float4*)g_scores)[i] = make_float4(0.f, 0.f, 0.f, 0.f);
}

// ---------------- persistent front-end (main stream, PROFILED slot 3) -------
__global__ __launch_bounds__(FE_THREADS) void k_frontend(
    const int* __restrict__ yt, const float* __restrict__ c_t_1,
    const float* __restrict__ s_t_1, const float* __restrict__ emb,
    const float* __restrict__ xc_w, const float* __restrict__ xc_b,
    const float* __restrict__ w_ih, const float* __restrict__ b_ih,
    const float* __restrict__ w_hh, const float* __restrict__ b_hh,
    const float* __restrict__ dp_w, const float* __restrict__ dp_b,
    const float* __restrict__ out1_b, const float* __restrict__ Wh,
    float* __restrict__ out_st, float* __restrict__ out_ct)
{
    int tid = threadIdx.x;
    int gt = blockIdx.x * FE_THREADS + tid;
    int gw = gt >> 5, lane = gt & 31;
    unsigned sense = 0;
    if (tid == 0) sense = atomicAdd(&g_barsense, 0u);

    // ---- S0: bias init, transposes, Wh->fp16, zero ct/concat-hi ----
    for (int idx = gt; idx < 4352 * 32; idx += FE_NT) {
        int n = idx >> 5, b = idx & 31;
        if (n < EE)     { g_xT[n * 32 + b] = xc_b[n];  continue; }  n -= EE;
        if (n < 3 * HH) { g_giT[n * 32 + b] = b_ih[n]; continue; }  n -= 3 * HH;
        if (n < 3 * HH) { g_ghT[n * 32 + b] = b_hh[n]; continue; }  n -= 3 * HH;
        if (n < HH)     { g_dec[b * HH + n] = dp_b[n]; continue; }  n -= HH;
        g_out1[b * HH + n] = out1_b[n];
    }
    for (int idx = gt; idx < (HH + EE) * BB; idx += FE_NT) {
        int k = idx >> 5, b = idx & 31;
        g_xinT[idx] = (k < HH) ? c_t_1[b * HH + k]
                               : emb[(size_t)yt[b] * EE + (k - HH)];
    }
    for (int idx = gt; idx < HH * BB; idx += FE_NT) {
        int k = idx >> 5, b = idx & 31;
        g_hT[idx] = s_t_1[b * HH + k];
    }
    for (int i = gt; i < HH * HH / 2; i += FE_NT) {
        float2 v = *(const float2*)(Wh + (size_t)i * 2);
        *(__half2*)(g_whh + (size_t)i * 2) = __floats2half2_rn(v.x, v.y);
    }
    for (int idx = gt; idx < HH * BB; idx += FE_NT) {
        g_concatT[HH * BB + idx] = 0.f;
        out_ct[idx] = 0.f;
    }
    grid_bar(&sense);

    // ---- S1: x ----
    {
        int n = gw >> 3, sp = gw & 7;
        int k0 = sp * 96;
        float r = dotk((const float4*)(xc_w + (size_t)n * (HH + EE) + k0),
                       g_xinT + k0 * 32 + lane, 24);
        atomicAdd(&g_xT[n * 32 + lane], r);
    }
    grid_bar(&sense);

    // ---- S2: gi + gh ----
    for (int u = gw; u < 9216; u += 2048) {
        if (u < 3072) {
            int n = u >> 1, sp = u & 1, k0 = sp * 128;
            float r = dotk((const float4*)(w_ih + (size_t)n * EE + k0),
                           g_xT + k0 * 32 + lane, 32);
            atomicAdd(&g_giT[n * 32 + lane], r);
        } else {
            int v = u - 3072;
            int n = v >> 2, sp = v & 3, k0 = sp * 128;
            float r = dotk((const float4*)(w_hh + (size_t)n * HH + k0),
                           g_hT + k0 * 32 + lane, 32);
            atomicAdd(&g_ghT[n * 32 + lane], r);
        }
    }
    grid_bar(&sense);

    // ---- S3: GRU ----
    if (gt < HH * BB) {
        int j = gt >> 5, b = gt & 31;
        float ir = g_giT[j * BB + b],             hr = g_ghT[j * BB + b];
        float iz = g_giT[(HH + j) * BB + b],      hz = g_ghT[(HH + j) * BB + b];
        float in_ = g_giT[(2 * HH + j) * BB + b], hn = g_ghT[(2 * HH + j) * BB + b];
        float r = sigmoidf_(ir + hr);
        float z = sigmoidf_(iz + hz);
        float nn = tanhf(in_ + r * hn);
        float h = g_hT[j * BB + b];
        float hv = (1.f - z) * nn + z * h;
        g_hnewT[j * BB + b] = hv;
        g_concatT[j * BB + b] = hv;
        out_st[b * HH + j] = hv;
    }
    grid_bar(&sense);

    // ---- S4: dec ----
    {
        int n = gw >> 2, sp = gw & 3, k0 = sp * 128;
        float r = dotk((const float4*)(dp_w + (size_t)n * HH + k0),
                       g_hnewT + k0 * 32 + lane, 32);
        atomicAdd(&g_dec[lane * HH + n], r);
    }
}

// ---------------- split-K small GEMM (out1; k_base selects K half) ----------
__global__ __launch_bounds__(256) void k_bsplit(float* __restrict__ yR,
                                                const float* __restrict__ AT,
                                                const float* __restrict__ W,
                                                int N, int K, int k_base) {
    int warp = threadIdx.x >> 5, lane = threadIdx.x & 31;
    int n = blockIdx.x * 8 + warp;
    int k0 = k_base + blockIdx.y * 128;
    float r = dotk((const float4*)(W + (size_t)n * K + k0),
                   AT + k0 * 32 + lane, 32);
    atomicAdd(&yR[(size_t)lane * N + n], r);
}

// ---------------- fused attention v3 -----------------------------------------
#define F3_STG   2304
#define F3_STGSZ 25600
#define F3_SMEM  (F3_STG + 2 * F3_STGSZ)     // 53504

#define F3_ISSUE(c, st) do {                                                    \
    uint32_t sb_ = smb + F3_STG + (st) * F3_STGSZ;                              \
    _Pragma("unroll")                                                           \
    for (int i_ = 0; i_ < 5; i_++) {                                            \
        int s_ = tid + (i_ << 8);                                               \
        if (i_ == 0) {                                                          \
            int r_ = s_ >> 2, q_ = s_ & 3;                                      \
            cp16(sb_ + r_ * 80 + q_ * 16,                                       \
                 g_ench + (m0 + r_) * HH + (c) * 32 + q_ * 8);                  \
        } else {                                                                \
            int t_ = s_ - 256, r_ = t_ >> 2, q_ = t_ & 3;                       \
            cp16(sb_ + 5120 + r_ * 80 + q_ * 16,                                \
                 g_whh + (size_t)(n0 + r_) * HH + (c) * 32 + q_ * 8);           \
        }                                                                       \
    }                                                                           \
    cp_commit();                                                                \
} while (0)

__global__ __launch_bounds__(256, 3) void k_fat3(const float* __restrict__ vw) {
    extern __shared__ char sm[];
    uint32_t smb = (uint32_t)__cvta_generic_to_shared(sm);
    float* sdec = (float*)(sm + 0);
    float* sv   = (float*)(sm + 1024);
    float* srow = (float*)(sm + 2048);

    int tid = threadIdx.x, warp = tid >> 5, lane = tid & 31;
    int bt = blockIdx.x, n0 = blockIdx.y << 8;
    int b = bt >> 4;
    size_t m0 = (size_t)bt * 64;

    sv[tid]   = vw[n0 + tid];
    sdec[tid] = g_dec[b * HH + n0 + tid];
    if (tid < 64) srow[tid] = 0.f;

    int wm = warp >> 2, wn = warp & 3;    // warp tile: 32 rows x 64 cols
    wmma::fragment<wmma::accumulator, 16, 16, 16, __half> acc[2][4];
#pragma unroll
    for (int i = 0; i < 2; i++)
#pragma unroll
        for (int j = 0; j < 4; j++) wmma::fill_fragment(acc[i][j], __float2half(0.f));

    F3_ISSUE(0, 0);

    for (int c = 0; c < 16; c++) {
        cp_wait<0>();
        __syncthreads();     // publishes stage c; retires stage c-1
        if (c < 15) F3_ISSUE(c + 1, (c + 1) & 1);
        const __half* ab = (const __half*)(sm + F3_STG + (c & 1) * F3_STGSZ);
        const __half* bb = ab + 2560;
#pragma unroll
        for (int kk = 0; kk < 32; kk += 16) {
            wmma::fragment<wmma::matrix_a, 16, 16, 16, __half, wmma::row_major> af[2];
#pragma unroll
            for (int i = 0; i < 2; i++)
                wmma::load_matrix_sync(af[i], ab + (wm * 32 + i * 16) * 40 + kk, 40);
#pragma unroll
            for (int j = 0; j < 4; j++) {
                wmma::fragment<wmma::matrix_b, 16, 16, 16, __half, wmma::col_major> bf;
                wmma::load_matrix_sync(bf, bb + (wn * 64 + j * 16) * 40 + kk, 40);
                wmma::mma_sync(acc[0][j], af[0], bf, acc[0][j]);
                wmma::mma_sync(acc[1][j], af[1], bf, acc[1][j]);
            }
        }
    }
    __syncthreads();   // protect stage buffers before scratch reuse

    __half* scr = (__half*)(sm + F3_STG) + warp * 1088;   // [16][68] halfs
#pragma unroll
    for (int i = 0; i < 2; i++) {
#pragma unroll
        for (int j = 0; j < 4; j++)
            wmma::store_matrix_sync(scr + j * 16, acc[i][j], 68, wmma::mem_row_major);
        __syncwarp();
        int row = lane >> 1, hf = lane & 1;
        const __half* sr = scr + row * 68;
        float p = 0.f;
#pragma unroll
        for (int c = 0; c < 32; c++) {
            int cl = wn * 64 + hf * 32 + c;
            p += sv[cl] * tanh_fast(__half2float(sr[hf * 32 + c]) + sdec[cl]);
        }
        p += __shfl_xor_sync(0xffffffffu, p, 1);
        if (hf == 0) atomicAdd(&srow[wm * 32 + i * 16 + row], p);
        __syncwarp();
    }
    __syncthreads();
    if (tid < 64) atomicAdd(&g_scores[bt * 64 + tid], srow[tid]);
}

// ---------------- merged attn softmax + c_t partial --------------------------
__global__ __launch_bounds__(512) void k_attn_ct(float* __restrict__ out_attn,
                                                 float* __restrict__ out_ct) {
    __shared__ float satt[1024];
    __shared__ float red[16];
    __shared__ float sa[64];
    int c = blockIdx.x, b = blockIdx.y, tid = threadIdx.x;   // 512 thr

    float s0 = g_scores[b * TKK + tid];
    float s1 = g_scores[b * TKK + 512 + tid];
    float m = fmaxf(s0, s1);
#pragma unroll
    for (int o = 16; o; o >>= 1) m = fmaxf(m, __shfl_xor_sync(0xffffffffu, m, o));
    if ((tid & 31) == 0) red[tid >> 5] = m;
    __syncthreads();
    if (tid < 32) {
        float v = (tid < 16) ? red[tid] : -1e30f;
#pragma unroll
        for (int o = 8; o; o >>= 1) v = fmaxf(v, __shfl_xor_sync(0xffffffffu, v, o));
        if (tid == 0) red[0] = v;
    }
    __syncthreads();
    float mx = red[0];
    __syncthreads();
    float e0 = __expf(s0 - mx), e1 = __expf(s1 - mx);
    float sm = e0 + e1;
#pragma unroll
    for (int o = 16; o; o >>= 1) sm += __shfl_xor_sync(0xffffffffu, sm, o);
    if ((tid & 31) == 0) red[tid >> 5] = sm;
    __syncthreads();
    if (tid < 32) {
        float v = (tid < 16) ? red[tid] : 0.f;
#pragma unroll
        for (int o = 8; o; o >>= 1) v += __shfl_xor_sync(0xffffffffu, v, o);
        if (tid == 0) red[0] = v;
    }
    __syncthreads();
    float inv = 1.f / red[0];
    satt[tid] = e0 * inv;
    satt[512 + tid] = e1 * inv;
    __syncthreads();
    if (tid < 64) {
        float a = satt[c * 64 + tid];
        out_attn[b * TKK + c * 64 + tid] = a;
        sa[tid] = a;
    }
    __syncthreads();
    const __half* e = g_ench + ((size_t)b * TKK + c * 64) * HH + tid;
    float acc = 0.f;
#pragma unroll 8
    for (int t = 0; t < 64; t++) acc += sa[t] * __half2float(e[(size_t)t * HH]);
    atomicAdd(&out_ct[b * HH + tid], acc);
    atomicAdd(&g_concatT[(HH + tid) * BB + b], acc);
}

// ---------------- logits via bf16 wmma + fused per-slab softmax stats -------
#define LG_SMEM (33280 + 20480)
__global__ __launch_bounds__(256) void k_logits_mma(const float* __restrict__ W,
                                                    const float* __restrict__ bias) {
    extern __shared__ char smraw[];
    __nv_bfloat16* As2 = (__nv_bfloat16*)smraw;                // [32][520]
    __nv_bfloat16* Ws  = (__nv_bfloat16*)(smraw + 33280);      // [2][128][40]
    float* stage = (float*)(smraw + 33280);                    // [32][136]

    int tid = threadIdx.x, warp = tid >> 5;
    int n0 = blockIdx.x * 128;
    for (int idx = tid; idx < BB * HH; idx += 256) {
        int r = idx >> 9, k = idx & 511;
        As2[r * 520 + k] = __float2bfloat16(g_out1[idx]);
    }

    wmma::fragment<wmma::accumulator, 16, 16, 16, float> acc[2];
    wmma::fill_fragment(acc[0], 0.f);
    wmma::fill_fragment(acc[1], 0.f);

    int lrow = tid >> 3, lq = tid & 7;
    float4 wreg[4];
#pragma unroll
    for (int p = 0; p < 4; p++) {
        int n = n0 + p * 32 + lrow;
        wreg[p] = (n < VOCAB) ? *(const float4*)(W + (size_t)n * HH + lq * 4)
                              : make_float4(0.f, 0.f, 0.f, 0.f);
    }
    for (int it = 0; it < 16; it++) {
        int cur = it & 1;
        __nv_bfloat16* wd = Ws + cur * (128 * 40);
#pragma unroll
        for (int p = 0; p < 4; p++) {
            __nv_bfloat16* d = wd + (p * 32 + lrow) * 40 + lq * 4;
            *(__nv_bfloat162*)d       = __floats2bfloat162_rn(wreg[p].x, wreg[p].y);
            *(__nv_bfloat162*)(d + 2) = __floats2bfloat162_rn(wreg[p].z, wreg[p].w);
        }
        if (it < 15) {
#pragma unroll
            for (int p = 0; p < 4; p++) {
                int n = n0 + p * 32 + lrow;
                wreg[p] = (n < VOCAB)
                    ? *(const float4*)(W + (size_t)n * HH + (it + 1) * 32 + lq * 4)
                    : make_float4(0.f, 0.f, 0.f, 0.f);
            }
        }
        __syncthreads();
#pragma unroll
        for (int kk = 0; kk < 32; kk += 16) {
            wmma::fragment<wmma::matrix_b, 16, 16, 16, __nv_bfloat16, wmma::col_major> bf;
            wmma::load_matrix_sync(bf, wd + (warp * 16) * 40 + kk, 40);
#pragma unroll
            for (int i = 0; i < 2; i++) {
                wmma::fragment<wmma::matrix_a, 16, 16, 16, __nv_bfloat16, wmma::row_major> af;
                wmma::load_matrix_sync(af, As2 + (i * 16) * 520 + it * 32 + kk, 520);
                wmma::mma_sync(acc[i], af, bf, acc[i]);
            }
        }
    }
    __syncthreads();
#pragma unroll
    for (int i = 0; i < 2; i++)
        wmma::store_matrix_sync(stage + (i * 16) * 136 + warp * 16, acc[i], 136,
                                wmma::mem_row_major);
    __syncthreads();
    for (int idx = tid; idx < 32 * 128; idx += 256) {
        int r = idx >> 7, c = idx & 127;
        int n = n0 + c;
        if (n < VOCAB)
            g_logits[(size_t)r * VOCAB + n] = stage[r * 136 + c] + bias[n];
    }
    // fused per-slab softmax stats
    {
        int l = tid & 31;
        int row = (tid >> 5) * 4 + (l >> 3);
        int c0 = l & 7;
        float mx = -1e30f;
        for (int c = c0; c < 128; c += 8) {
            int n = n0 + c;
            if (n < VOCAB) mx = fmaxf(mx, stage[row * 136 + c] + bias[n]);
        }
#pragma unroll
        for (int o = 4; o; o >>= 1) mx = fmaxf(mx, __shfl_xor_sync(0xffffffffu, mx, o));
        float sm = 0.f;
        for (int c = c0; c < 128; c += 8) {
            int n = n0 + c;
            if (n < VOCAB) sm += __expf(stage[row * 136 + c] + bias[n] - mx);
        }
#pragma unroll
        for (int o = 4; o; o >>= 1) sm += __shfl_xor_sync(0xffffffffu, sm, o);
        if (c0 == 0) {
            g_smx[row * 400 + blockIdx.x] = mx;
            g_sms[row * 400 + blockIdx.x] = sm;
        }
    }
}

// ---------------- vocab softmax normalize ------------------------------------
__global__ __launch_bounds__(256) void k_smB(float* __restrict__ out_fd) {
    __shared__ float red[16];
    int b = blockIdx.y, tid = threadIdx.x;
    float m = -1e30f;
    for (int s = tid; s < NSLAB; s += 256) m = fmaxf(m, g_smx[b * 400 + s]);
#pragma unroll
    for (int o = 16; o; o >>= 1) m = fmaxf(m, __shfl_xor_sync(0xffffffffu, m, o));
    if ((tid & 31) == 0) red[tid >> 5] = m;
    __syncthreads();
    if (tid < 32) {
        float v = (tid < 8) ? red[tid] : -1e30f;
#pragma unroll
        for (int o = 4; o; o >>= 1) v = fmaxf(v, __shfl_xor_sync(0xffffffffu, v, o));
        if (tid == 0) red[0] = v;
    }
    __syncthreads();
    float M = red[0];
    __syncthreads();
    float s = 0.f;
    for (int sl = tid; sl < NSLAB; sl += 256)
        s += g_sms[b * 400 + sl] * __expf(g_smx[b * 400 + sl] - M);
#pragma unroll
    for (int o = 16; o; o >>= 1) s += __shfl_xor_sync(0xffffffffu, s, o);
    if ((tid & 31) == 0) red[tid >> 5] = s;
    __syncthreads();
    if (tid < 32) {
        float v = (tid < 8) ? red[tid] : 0.f;
#pragma unroll
        for (int o = 4; o; o >>= 1) v += __shfl_xor_sync(0xffffffffu, v, o);
        if (tid == 0) red[0] = v;
    }
    __syncthreads();
    float inv = 1.f / red[0];
    const float* lg = g_logits + (size_t)b * VOCAB;
    float* dst = out_fd + (size_t)b * VOCAB;
    int base = blockIdx.x * 2048;
#pragma unroll
    for (int j = 0; j < 8; j++) {
        int n = base + j * 256 + tid;
        if (n < VOCAB) dst[n] = __expf(lg[n] - M) * inv;
    }
}

// ---------------- launcher ---------------------------------------------------
extern "C" void kernel_launch(void* const* d_in, const int* in_sizes, int n_in,
                              void* d_out, int out_size) {
    const int*   y      = (const int*)d_in[0];
    const float* s_t_1  = (const float*)d_in[2];
    const float* enc    = (const float*)d_in[3];
    const float* c_t_1  = (const float*)d_in[4];
    const float* cov    = (const float*)d_in[5];
    const float* emb    = (const float*)d_in[7];
    const float* xc_w   = (const float*)d_in[8];
    const float* xc_b   = (const float*)d_in[9];
    const float* Wh_w   = (const float*)d_in[10];
    const float* w_ih   = (const float*)d_in[11];
    const float* w_hh   = (const float*)d_in[12];
    const float* b_ih   = (const float*)d_in[13];
    const float* b_hh   = (const float*)d_in[14];
    const float* dp_w   = (const float*)d_in[15];
    const float* dp_b   = (const float*)d_in[16];
    const float* v_w    = (const float*)d_in[17];
    const float* out1_w = (const float*)d_in[18];
    const float* out1_b = (const float*)d_in[19];
    const float* out2_w = (const float*)d_in[20];
    const float* out2_b = (const float*)d_in[21];

    float* out      = (float*)d_out;
    float* out_fd   = out;
    float* out_st   = out_fd + (size_t)BB * VOCAB;
    float* out_ct   = out_st + BB * HH;
    float* out_attn = out_ct + BB * HH;
    float* out_cov  = out_attn + BB * TKK;

    float *p_concatT, *p_out1;
    cudaGetSymbolAddress((void**)&p_concatT, g_concatT);
    cudaGetSymbolAddress((void**)&p_out1,    g_out1);

    static cudaStream_t s2 = nullptr;
    static cudaEvent_t evF = nullptr, evJ = nullptr, evH = nullptr, evH2 = nullptr;
    if (!s2) {
        cudaStreamCreateWithFlags(&s2, cudaStreamNonBlocking);
        cudaEventCreateWithFlags(&evF, cudaEventDisableTiming);
        cudaEventCreateWithFlags(&evJ, cudaEventDisableTiming);
        cudaEventCreateWithFlags(&evH, cudaEventDisableTiming);
        cudaEventCreateWithFlags(&evH2, cudaEventDisableTiming);
        cudaFuncSetAttribute(k_fat3, cudaFuncAttributeMaxDynamicSharedMemorySize, F3_SMEM);
        cudaFuncSetAttribute(k_logits_mma, cudaFuncAttributeMaxDynamicSharedMemorySize, LG_SMEM);
    }

    // fork: converts + zero + cov copy on side stream; front-end on main
    cudaEventRecord(evF, 0);
    cudaStreamWaitEvent(s2, evF, 0);
    k_convert_enc<<<4096, 256, 0, s2>>>(enc, 0);                           // launch 0
    k_convert_enc<<<4096, 256, 0, s2>>>(enc, 1048576);                     // launch 1
    k_zero_scores<<<BB * TKK / 1024, 256, 0, s2>>>();                      // launch 2
    cudaMemcpyAsync(out_cov, cov, (size_t)BB * TKK * sizeof(float),
                    cudaMemcpyDeviceToDevice, s2);
    cudaEventRecord(evJ, s2);
    k_frontend<<<FE_BLOCKS, FE_THREADS>>>(y, c_t_1, s_t_1, emb,
                                          xc_w, xc_b, w_ih, b_ih, w_hh, b_hh,
                                          dp_w, dp_b, out1_b, Wh_w,
                                          out_st, out_ct);                 // launch 3 <- PROFILED
    // out1 h-half overlaps fat3 on side stream
    cudaEventRecord(evH, 0);
    cudaStreamWaitEvent(s2, evH, 0);
    k_bsplit<<<dim3(HH / 8, 4), 256, 0, s2>>>(p_out1, p_concatT, out1_w,
                                              HH, 2 * HH, 0);              // launch 4 (s2)
    cudaEventRecord(evH2, s2);
    // main: fat3 waits converts+zero
    cudaStreamWaitEvent(0, evJ, 0);
    k_fat3<<<dim3(M_ENC / 64, 2), 256, F3_SMEM>>>(v_w);                    // launch 5
    k_attn_ct<<<dim3(16, BB), 512>>>(out_attn, out_ct);                    // launch 6
    k_bsplit<<<dim3(HH / 8, 4), 256>>>(p_out1, p_concatT, out1_w,
                                       HH, 2 * HH, HH);                    // launch 7
    cudaStreamWaitEvent(0, evH2, 0);
    k_logits_mma<<<(VOCAB + 127) / 128, 256, LG_SMEM>>>(out2_w, out2_b);   // launch 8
    k_smB<<<dim3(25, BB), 256>>>(out_fd);                                  // launch 9
}